// round 8
// baseline (speedup 1.0000x reference)
#include <cuda_runtime.h>
#include <math.h>

#define N_PTS   8192
#define GDIM    12
#define NCELLS  1728                          // 12^3
#define CELL_H  0.025f
#define INV_H   40.0f
#define H2      6.25e-4f                      // 0.025^2
#define THR2    4.0e-4f                       // 0.02^2
#define BIGF    1.0e30f
#define CAP     32                            // bucket capacity (mean 4.7/cell)
#define NSUPER  432                           // 6*6*12 supercells (2x2x1 cells)
#define SMEM_CAND 640                         // region candidate capacity

// ---------------- device scratch (no allocations allowed) ----------------
__device__ int    g_cnt[NCELLS];              // zero-init; last block restores
__device__ int    g_ready;                    // zero-init; last block restores
__device__ int    g_done;                     // zero-init; last block restores
__device__ float4 g_bpos[NCELLS * CAP];       // bucketed (x,y,z,|p|^2)
__device__ float4 g_bquat[NCELLS * CAP];
__device__ int    g_borig[NCELLS * CAP];
__device__ float  g_flat[N_PTS];
__device__ float4 g_part[NSUPER];             // per-block partials (F,D,A,C)

// ---------------- helpers ----------------
__device__ __forceinline__ void insert9(float (&t)[9], float d) {
    if (d < t[8]) {
        t[8] = d;
        #pragma unroll
        for (int k = 8; k > 0; --k) {
            float lo = fminf(t[k - 1], t[k]);
            float hi = fmaxf(t[k - 1], t[k]);
            t[k - 1] = lo;
            t[k]     = hi;
        }
    }
}

// Warp-collective extraction (fallback path only).
__device__ __forceinline__ float knn_mean_warp(float (&t)[9], int lane) {
    float sum = 0.0f, mn = 0.0f;
    #pragma unroll
    for (int r = 0; r < 9; ++r) {
        float cand = t[0];
        float v = cand;
        #pragma unroll
        for (int off = 16; off > 0; off >>= 1)
            v = fminf(v, __shfl_xor_sync(0xffffffffu, v, off));
        unsigned m = __ballot_sync(0xffffffffu, cand == v);
        if (lane == (__ffs(m) - 1)) {
            #pragma unroll
            for (int k = 0; k < 8; ++k) t[k] = t[k + 1];
            t[8] = BIGF;
        }
        float d = sqrtf(fmaxf(v, 0.0f) + 1e-12f);
        if (r == 0) mn = d;
        sum += d;
    }
    return (sum - mn) * 0.125f;
}

// ---------------- single fused kernel ----------------
__global__ __launch_bounds__(32)
void fused_k(const float*  __restrict__ pos,
             const float4* __restrict__ rot,
             const float*  __restrict__ scales,
             const float*  __restrict__ opacity,
             float* __restrict__ out) {
    __shared__ float4 s_p[SMEM_CAND];
    __shared__ float4 s_q[SMEM_CAND];
    __shared__ int    s_id[SMEM_CAND];
    __shared__ int    s_coff[49];             // region prefix offsets
    __shared__ int    s_cbase[48];            // bucket base per region cell

    const int b    = blockIdx.x;
    const int lane = threadIdx.x;

    // ---------- phase 1: bin my point + flatness ----------
    {
        int i = b * 32 + lane;
        if (i < N_PTS) {
            float x = pos[3 * i + 0], y = pos[3 * i + 1], z = pos[3 * i + 2];
            int cx = min(GDIM - 1, max(0, (int)(x * INV_H)));
            int cy = min(GDIM - 1, max(0, (int)(y * INV_H)));
            int cz = min(GDIM - 1, max(0, (int)(z * INV_H)));
            int cid = (cz * GDIM + cy) * GDIM + cx;
            int slot = atomicAdd(&g_cnt[cid], 1);
            if (slot < CAP) {
                int dst = cid * CAP + slot;
                g_bpos[dst]  = make_float4(x, y, z, fmaf(x, x, fmaf(y, y, z * z)));
                g_bquat[dst] = rot[i];
                g_borig[dst] = i;
            }
            float a = expf(scales[3 * i + 0]);
            float bb = expf(scales[3 * i + 1]);
            float c = expf(scales[3 * i + 2]);
            float tt;
            if (a > bb) { tt = a; a = bb; bb = tt; }
            if (bb > c) { tt = bb; bb = c; c = tt; }
            if (a > bb) { tt = a; a = bb; bb = tt; }
            g_flat[i] = logf(c / (a + 1e-8f) + 1e-8f) + 0.1f / (fabsf(c - bb) + 0.001f);
        }
    }
    // device-wide barrier (all 432 one-warp blocks are resident by construction)
    __threadfence();
    if (lane == 0) {
        atomicAdd(&g_ready, 1);
        while (atomicAdd(&g_ready, 0) < NSUPER) __nanosleep(64);
    }
    __syncwarp();
    __threadfence();

    // ---------- phase 2: supercell setup ----------
    const int sx = b % 6, sy = (b / 6) % 6, sz = b / 36;
    const int rx0 = max(2 * sx - 1, 0), rx1 = min(2 * sx + 2, GDIM - 1);
    const int ry0 = max(2 * sy - 1, 0), ry1 = min(2 * sy + 2, GDIM - 1);
    const int rz0 = max(sz - 1, 0),     rz1 = min(sz + 1, GDIM - 1);
    const int nx = rx1 - rx0 + 1, nyc = ry1 - ry0 + 1, nzc = rz1 - rz0 + 1;
    const int RC = nx * nyc * nzc;            // <= 48

    // parallel counts + 2-segment warp scan -> prefix offsets
    {
        int c0 = 0, c1 = 0;
        if (lane < RC) {
            int lx = lane % nx, rem = lane / nx;
            int cid = ((rz0 + rem / nyc) * GDIM + (ry0 + rem % nyc)) * GDIM + (rx0 + lx);
            s_cbase[lane] = cid * CAP;
            c0 = min(g_cnt[cid], CAP);
        }
        int t2 = lane + 32;
        if (t2 < RC) {
            int lx = t2 % nx, rem = t2 / nx;
            int cid = ((rz0 + rem / nyc) * GDIM + (ry0 + rem % nyc)) * GDIM + (rx0 + lx);
            s_cbase[t2] = cid * CAP;
            c1 = min(g_cnt[cid], CAP);
        }
        int v = c0;
        #pragma unroll
        for (int o = 1; o < 32; o <<= 1) {
            int u = __shfl_up_sync(0xffffffffu, v, o);
            if (lane >= o) v += u;
        }
        if (lane < RC) s_coff[lane + 1] = v;
        int tot0 = __shfl_sync(0xffffffffu, v, 31);
        int w = c1;
        #pragma unroll
        for (int o = 1; o < 32; o <<= 1) {
            int u = __shfl_up_sync(0xffffffffu, w, o);
            if (lane >= o) w += u;
        }
        if (t2 < RC) s_coff[t2 + 1] = w + tot0;
        if (lane == 0) s_coff[0] = 0;
    }
    __syncwarp();

    const int total = s_coff[RC];
    const bool oversize = (total > SMEM_CAND);

    if (!oversize) {
        for (int idx = lane; idx < total; idx += 32) {
            int lo = 0, hi = RC - 1;
            #pragma unroll
            for (int s = 0; s < 6; ++s) {
                int mid = (lo + hi + 1) >> 1;
                if (s_coff[mid] <= idx) lo = mid; else hi = mid - 1;
            }
            int src = s_cbase[lo] + (idx - s_coff[lo]);
            s_p[idx]  = g_bpos[src];
            s_q[idx]  = g_bquat[src];
            s_id[idx] = g_borig[src];
        }
    }
    __syncwarp();

    // home cells (2x2x1) -> region-local offsets
    int h_off[4], h_cnt[4], h_base[4];
    #pragma unroll
    for (int d = 0; d < 4; ++d) {
        int hx = 2 * sx + (d & 1), hy = 2 * sy + ((d >> 1) & 1);
        int rl = (hx - rx0) + nx * ((hy - ry0) + nyc * (sz - rz0));
        h_off[d]  = s_coff[rl];
        h_cnt[d]  = s_coff[rl + 1] - s_coff[rl];
        h_base[d] = s_cbase[rl];
    }
    const int c1s = h_cnt[0], c2s = c1s + h_cnt[1], c3s = c2s + h_cnt[2];
    const int totalRows = c3s + h_cnt[3];

    float Fp = 0.0f, Dp = 0.0f, Ap = 0.0f, Cp = 0.0f;

    for (int r0 = 0; r0 < totalRows; r0 += 32) {
        const int r = r0 + lane;
        const bool active = (r < totalRows);
        const int rr = active ? r : 0;
        int dsel, loc;
        if      (rr < c1s) { dsel = 0; loc = rr; }
        else if (rr < c2s) { dsel = 1; loc = rr - c1s; }
        else if (rr < c3s) { dsel = 2; loc = rr - c2s; }
        else               { dsel = 3; loc = rr - c3s; }
        const int myIdx  = h_off[dsel] + loc;       // smem index of own row
        const int mySrc  = h_base[dsel] + loc;      // gmem bucket slot of own row

        float4 P, Q;
        int myid;
        if (!oversize) { P = s_p[myIdx]; Q = s_q[myIdx]; myid = s_id[myIdx]; }
        else           { P = g_bpos[mySrc]; Q = g_bquat[mySrc]; myid = g_borig[mySrc]; }

        float t[9];
        #pragma unroll
        for (int k = 0; k < 9; ++k) t[k] = H2;   // sentinel: survives => fallback
        float asum = 0.0f, acnt = 0.0f;

        if (!oversize) {
            #pragma unroll 2
            for (int j = 0; j < total; ++j) {     // uniform loop: LDS broadcast
                float4 p = s_p[j];
                float dot = fmaf(P.x, p.x, fmaf(P.y, p.y, P.z * p.z));
                float d2  = fmaf(-2.0f, dot, P.w + p.w);
                insert9(t, d2);
                if (d2 < THR2 && j != myIdx) {
                    float4 q = s_q[j];
                    float qd = fmaf(Q.x, q.x, fmaf(Q.y, q.y, fmaf(Q.z, q.z, Q.w * q.w)));
                    asum += 1.0f - fabsf(qd);
                    acnt += 1.0f;
                }
            }
        } else {
            for (int c = 0; c < RC; ++c) {
                int cnt2 = s_coff[c + 1] - s_coff[c];
                int b2 = s_cbase[c];
                for (int j = 0; j < cnt2; ++j) {  // uniform: LDG broadcast
                    float4 p = g_bpos[b2 + j];
                    float dot = fmaf(P.x, p.x, fmaf(P.y, p.y, P.z * p.z));
                    float d2  = fmaf(-2.0f, dot, P.w + p.w);
                    insert9(t, d2);
                    if (d2 < THR2 && (b2 + j) != mySrc) {
                        float4 q = g_bquat[b2 + j];
                        float qd = fmaf(Q.x, q.x, fmaf(Q.y, q.y, fmaf(Q.z, q.z, Q.w * q.w)));
                        asum += 1.0f - fabsf(qd);
                        acnt += 1.0f;
                    }
                }
            }
        }

        // per-thread kNN: t[0] = self, t[1..8] = 8 nearest
        float knn = 0.0f;
        #pragma unroll
        for (int k = 1; k < 9; ++k) knn += sqrtf(fmaxf(t[k], 0.0f) + 1e-12f);
        knn *= 0.125f;
        const bool ok = (t[8] < H2);

        // rare exact fallback: warp-cooperative brute force over all points
        unsigned bad = __ballot_sync(0xffffffffu, active && !ok);
        while (bad) {
            int src = __ffs(bad) - 1;
            bad &= bad - 1;
            float4 Pb;
            Pb.x = __shfl_sync(0xffffffffu, P.x, src);
            Pb.y = __shfl_sync(0xffffffffu, P.y, src);
            Pb.z = __shfl_sync(0xffffffffu, P.z, src);
            Pb.w = __shfl_sync(0xffffffffu, P.w, src);
            float tb[9];
            #pragma unroll
            for (int k = 0; k < 9; ++k) tb[k] = BIGF;
            for (int j = lane; j < N_PTS; j += 32) {
                float px = pos[3 * j + 0], py = pos[3 * j + 1], pz = pos[3 * j + 2];
                float sqj = fmaf(px, px, fmaf(py, py, pz * pz));
                float dot = fmaf(Pb.x, px, fmaf(Pb.y, py, Pb.z * pz));
                float d2  = fmaf(-2.0f, dot, Pb.w + sqj);
                insert9(tb, d2);
            }
            float kv = knn_mean_warp(tb, lane);   // warp-uniform
            if (lane == src) knn = kv;
        }

        if (active) {
            Ap += asum;
            Cp += acnt;
            Dp += fabsf(knn - 0.01f) * opacity[myid];
            Fp += g_flat[myid];
        }
    }

    // ---------- block (one warp) reduce + last-block-done final ----------
    #pragma unroll
    for (int o = 16; o > 0; o >>= 1) {
        Fp += __shfl_down_sync(0xffffffffu, Fp, o);
        Dp += __shfl_down_sync(0xffffffffu, Dp, o);
        Ap += __shfl_down_sync(0xffffffffu, Ap, o);
        Cp += __shfl_down_sync(0xffffffffu, Cp, o);
    }
    int old = 0;
    if (lane == 0) {
        g_part[b] = make_float4(Fp, Dp, Ap, Cp);
        __threadfence();
        old = atomicAdd(&g_done, 1);
    }
    old = __shfl_sync(0xffffffffu, old, 0);

    if (old == NSUPER - 1) {                   // last block: final reduction
        float F = 0.0f, D = 0.0f, A = 0.0f, C = 0.0f;
        #pragma unroll
        for (int k = 0; k < 14; ++k) {
            int idx = lane + k * 32;
            if (idx < NSUPER) {
                float4 v = g_part[idx];
                F += v.x; D += v.y; A += v.z; C += v.w;
            }
        }
        #pragma unroll
        for (int o = 16; o > 0; o >>= 1) {
            F += __shfl_down_sync(0xffffffffu, F, o);
            D += __shfl_down_sync(0xffffffffu, D, o);
            A += __shfl_down_sync(0xffffffffu, A, o);
            C += __shfl_down_sync(0xffffffffu, C, o);
        }
        if (lane == 0) {
            float flatness_loss  = -(F / (float)N_PTS);
            float alignment_loss = (C > 0.0f) ? (A / C) : 0.0f;
            float density_loss   = D / (float)N_PTS;
            out[0] = flatness_loss + 0.5f * alignment_loss + 0.2f * density_loss;
            g_done = 0;
            g_ready = 0;
        }
        // restore bucket counters for next graph replay
        for (int k = lane; k < NCELLS; k += 32) g_cnt[k] = 0;
    }
}

// ---------------- launch ----------------
extern "C" void kernel_launch(void* const* d_in, const int* in_sizes, int n_in,
                              void* d_out, int out_size) {
    const float*  positions = (const float*)d_in[0];
    const float4* rotations = (const float4*)d_in[1];
    const float*  scales    = (const float*)d_in[2];
    const float*  opacity   = (const float*)d_in[3];
    float* out = (float*)d_out;

    fused_k<<<NSUPER, 32>>>(positions, rotations, scales, opacity, out);
}

// round 11
// speedup vs baseline: 11.2490x; 11.2490x over previous
#include <cuda_runtime.h>
#include <math.h>

#define N_PTS   8192
#define GDIM    8
#define NCELLS  512
#define INV_H   26.666666666666668f           // 1 / 0.0375
#define H2      0.00140625f                   // 0.0375^2
#define THR2    4.0e-4f                       // 0.02^2
#define BIGF    1.0e30f
#define CAP     48                            // bucket capacity (mean 16/cell)
#define SMEM_CAND 640                         // region candidate capacity
#define NBLK    512
#define NTHR    128

// ---------------- device scratch (no allocations allowed) ----------------
__device__ int    g_cnt[NCELLS];              // zero-init; main_k last block restores
__device__ int    g_done;                     // zero-init; main_k last block restores
__device__ float4 g_bpos[NCELLS * CAP];       // bucketed (x,y,z,|p|^2)
__device__ float4 g_bquat[NCELLS * CAP];
__device__ int    g_borig[NCELLS * CAP];
__device__ float  g_flat[N_PTS];
__device__ float4 g_part[NBLK];               // per-block partials (F,D,A,C)

// ---------------- helpers ----------------
__device__ __forceinline__ void insert9(float (&t)[9], float d) {
    if (d < t[8]) {
        t[8] = d;
        #pragma unroll
        for (int k = 8; k > 0; --k) {
            float lo = fminf(t[k - 1], t[k]);
            float hi = fmaxf(t[k - 1], t[k]);
            t[k - 1] = lo;
            t[k]     = hi;
        }
    }
}

// Full-warp collective extraction (exact fallback path only).
__device__ __forceinline__ float knn_mean_warp(float (&t)[9], int lane) {
    float sum = 0.0f, mn = 0.0f;
    #pragma unroll
    for (int r = 0; r < 9; ++r) {
        float cand = t[0];
        float v = cand;
        #pragma unroll
        for (int off = 16; off > 0; off >>= 1)
            v = fminf(v, __shfl_xor_sync(0xffffffffu, v, off));
        unsigned m = __ballot_sync(0xffffffffu, cand == v);
        if (lane == (__ffs(m) - 1)) {
            #pragma unroll
            for (int k = 0; k < 8; ++k) t[k] = t[k + 1];
            t[8] = BIGF;
        }
        float d = sqrtf(fmaxf(v, 0.0f) + 1e-12f);
        if (r == 0) mn = d;
        sum += d;
    }
    return (sum - mn) * 0.125f;
}

// ---------------- scatter: bucket points + per-point flatness ----------------
__global__ __launch_bounds__(256)
void scatter_k(const float* __restrict__ pos,
               const float4* __restrict__ rot,
               const float* __restrict__ scales) {
    int i = blockIdx.x * 256 + threadIdx.x;

    float x = pos[3 * i + 0], y = pos[3 * i + 1], z = pos[3 * i + 2];
    int cx = min(GDIM - 1, max(0, (int)(x * INV_H)));
    int cy = min(GDIM - 1, max(0, (int)(y * INV_H)));
    int cz = min(GDIM - 1, max(0, (int)(z * INV_H)));
    int cid = (cz * GDIM + cy) * GDIM + cx;

    int slot = atomicAdd(&g_cnt[cid], 1);
    if (slot < CAP) {
        int dst = cid * CAP + slot;
        g_bpos[dst]  = make_float4(x, y, z, fmaf(x, x, fmaf(y, y, z * z)));
        g_bquat[dst] = rot[i];
        g_borig[dst] = i;
    }

    float a = expf(scales[3 * i + 0]);
    float b = expf(scales[3 * i + 1]);
    float c = expf(scales[3 * i + 2]);
    float tt;
    if (a > b) { tt = a; a = b; b = tt; }
    if (b > c) { tt = b; b = c; c = tt; }
    if (a > b) { tt = a; a = b; b = tt; }
    g_flat[i] = logf(c / (a + 1e-8f) + 1e-8f) + 0.1f / (fabsf(c - b) + 0.001f);
}

// ---------------- main: block per cell, quad per row, fused final ----------------
__global__ __launch_bounds__(NTHR)
void main_k(const float*  __restrict__ pos,
            const float*  __restrict__ opacity,
            float* __restrict__ out) {
    __shared__ float4 s_p[SMEM_CAND];
    __shared__ float4 s_q[SMEM_CAND];
    __shared__ int    s_id[SMEM_CAND];
    __shared__ int    s_off[28];
    __shared__ int    s_base[27];
    __shared__ float  s_w[4][4];
    __shared__ int    s_last;

    const int cell = blockIdx.x;
    const int tid  = threadIdx.x;
    const int lane = tid & 31;
    const int warp = tid >> 5;

    // ---------- region setup (warp 0) ----------
    const int cx = cell & 7, cy = (cell >> 3) & 7, cz = cell >> 6;
    const int x0 = max(cx - 1, 0), x1 = min(cx + 1, 7);
    const int y0 = max(cy - 1, 0), y1 = min(cy + 1, 7);
    const int z0 = max(cz - 1, 0), z1 = min(cz + 1, 7);
    const int nx = x1 - x0 + 1, ny = y1 - y0 + 1, nz = z1 - z0 + 1;
    const int RC = nx * ny * nz;              // <= 27

    if (tid < 32) {
        int cnt2 = 0;
        if (tid < RC) {
            int lx = tid % nx, rem = tid / nx;
            int cid = ((z0 + rem / ny) * GDIM + (y0 + rem % ny)) * GDIM + (x0 + lx);
            s_base[tid] = cid * CAP;
            cnt2 = min(g_cnt[cid], CAP);
        }
        int v = cnt2;
        #pragma unroll
        for (int o = 1; o < 32; o <<= 1) {
            int u = __shfl_up_sync(0xffffffffu, v, o);
            if (lane >= o) v += u;
        }
        if (tid < 27) s_off[tid + 1] = v;
        if (tid == 0) s_off[0] = 0;
    }
    __syncthreads();

    const int total = s_off[RC];
    const bool oversize = (total > SMEM_CAND);

    if (!oversize) {
        for (int idx = tid; idx < total; idx += NTHR) {
            int lo = 0, hi = RC - 1;
            #pragma unroll
            for (int s = 0; s < 5; ++s) {
                int mid = (lo + hi + 1) >> 1;
                if (s_off[mid] <= idx) lo = mid; else hi = mid - 1;
            }
            int src = s_base[lo] + (idx - s_off[lo]);
            s_p[idx]  = g_bpos[src];
            s_q[idx]  = g_bquat[src];
            s_id[idx] = g_borig[src];
        }
    }
    __syncthreads();

    const int hc = (cx - x0) + nx * ((cy - y0) + ny * (cz - z0));
    const int ho = s_off[hc];
    const int myCnt = s_off[hc + 1] - ho;
    const int passes = (myCnt + 31) >> 5;     // uniform across block

    float Fp = 0.0f, Dp = 0.0f, Ap = 0.0f, Cp = 0.0f;

    for (int pass = 0; pass < passes; ++pass) {
        const int q   = (tid >> 2) + (pass << 5);   // row within home cell
        const int sub = tid & 3;                    // quad sub-thread
        const bool active = (q < myCnt);
        const int qs = active ? q : 0;
        const int myIdx = ho + qs;
        const int mySrc = cell * CAP + qs;

        float4 P, Q;
        int myid;
        if (!oversize) { P = s_p[myIdx]; Q = s_q[myIdx]; myid = s_id[myIdx]; }
        else           { P = g_bpos[mySrc]; Q = g_bquat[mySrc]; myid = g_borig[mySrc]; }

        float t[9];
        #pragma unroll
        for (int k = 0; k < 9; ++k) t[k] = H2;   // sentinel: 9th >= H2 => fallback
        float asum = 0.0f, acnt = 0.0f;

        if (!oversize) {
            for (int j = sub; j < total; j += 4) {
                float4 p = s_p[j];
                float dot = fmaf(P.x, p.x, fmaf(P.y, p.y, P.z * p.z));
                float d2  = fmaf(-2.0f, dot, P.w + p.w);
                insert9(t, d2);
                if (d2 < THR2 && j != myIdx) {       // alignment exact: 0.02 < h
                    float4 qq = s_q[j];
                    float qd = fmaf(Q.x, qq.x, fmaf(Q.y, qq.y, fmaf(Q.z, qq.z, Q.w * qq.w)));
                    asum += 1.0f - fabsf(qd);
                    acnt += 1.0f;
                }
            }
        } else {
            for (int c = 0; c < RC; ++c) {
                int cnt2 = s_off[c + 1] - s_off[c];
                int b2 = s_base[c];
                for (int j = sub; j < cnt2; j += 4) {
                    int slot = b2 + j;
                    float4 p = g_bpos[slot];
                    float dot = fmaf(P.x, p.x, fmaf(P.y, p.y, P.z * p.z));
                    float d2  = fmaf(-2.0f, dot, P.w + p.w);
                    insert9(t, d2);
                    if (d2 < THR2 && slot != mySrc) {
                        float4 qq = g_bquat[slot];
                        float qd = fmaf(Q.x, qq.x, fmaf(Q.y, qq.y, fmaf(Q.z, qq.z, Q.w * qq.w)));
                        asum += 1.0f - fabsf(qd);
                        acnt += 1.0f;
                    }
                }
            }
        }

        // quad-reduce alignment partials
        asum += __shfl_xor_sync(0xffffffffu, asum, 1);
        asum += __shfl_xor_sync(0xffffffffu, asum, 2);
        acnt += __shfl_xor_sync(0xffffffffu, acnt, 1);
        acnt += __shfl_xor_sync(0xffffffffu, acnt, 2);

        // quad-merge: 9 smallest of 4 sorted lists; drop global min (self)
        float sum = 0.0f, mn = 0.0f, last = 0.0f;
        #pragma unroll
        for (int r = 0; r < 9; ++r) {
            float cand = t[0];
            float v = fminf(cand, __shfl_xor_sync(0xffffffffu, cand, 1));
            v = fminf(v, __shfl_xor_sync(0xffffffffu, v, 2));
            unsigned blt = __ballot_sync(0xffffffffu, cand == v);
            int qb = lane & ~3;
            int leader = qb + __ffs((blt >> qb) & 0xfu) - 1;
            if (lane == leader) {
                #pragma unroll
                for (int k = 0; k < 8; ++k) t[k] = t[k + 1];
                t[8] = BIGF;
            }
            float d = sqrtf(fmaxf(v, 0.0f) + 1e-12f);
            if (r == 0) mn = d;
            sum += d;
            if (r == 8) last = v;
        }
        float knn = (sum - mn) * 0.125f;
        const bool ok = (last < H2);

        // rare exact fallback: warp-cooperative brute force over all points
        unsigned bad = __ballot_sync(0xffffffffu, active && !ok && (sub == 0));
        while (bad) {
            int src = __ffs(bad) - 1;
            bad &= bad - 1;
            float4 Pb;
            Pb.x = __shfl_sync(0xffffffffu, P.x, src);
            Pb.y = __shfl_sync(0xffffffffu, P.y, src);
            Pb.z = __shfl_sync(0xffffffffu, P.z, src);
            Pb.w = __shfl_sync(0xffffffffu, P.w, src);
            float tb[9];
            #pragma unroll
            for (int k = 0; k < 9; ++k) tb[k] = BIGF;
            for (int j = lane; j < N_PTS; j += 32) {
                float px = pos[3 * j + 0], py = pos[3 * j + 1], pz = pos[3 * j + 2];
                float sqj = fmaf(px, px, fmaf(py, py, pz * pz));
                float dot = fmaf(Pb.x, px, fmaf(Pb.y, py, Pb.z * pz));
                float d2  = fmaf(-2.0f, dot, Pb.w + sqj);
                insert9(tb, d2);
            }
            float kv = knn_mean_warp(tb, lane);   // warp-uniform
            if (lane == src) knn = kv;
        }

        if (active && sub == 0) {
            Ap += asum;
            Cp += acnt;
            Dp += fabsf(knn - 0.01f) * opacity[myid];
            Fp += g_flat[myid];
        }
    }

    // ---------- block reduce + last-block-done final ----------
    #pragma unroll
    for (int o = 16; o > 0; o >>= 1) {
        Fp += __shfl_down_sync(0xffffffffu, Fp, o);
        Dp += __shfl_down_sync(0xffffffffu, Dp, o);
        Ap += __shfl_down_sync(0xffffffffu, Ap, o);
        Cp += __shfl_down_sync(0xffffffffu, Cp, o);
    }
    if (lane == 0) { s_w[warp][0] = Fp; s_w[warp][1] = Dp; s_w[warp][2] = Ap; s_w[warp][3] = Cp; }
    __syncthreads();
    if (tid == 0) {
        float4 bp = make_float4(0.0f, 0.0f, 0.0f, 0.0f);
        #pragma unroll
        for (int w = 0; w < 4; ++w) {
            bp.x += s_w[w][0]; bp.y += s_w[w][1];
            bp.z += s_w[w][2]; bp.w += s_w[w][3];
        }
        g_part[cell] = bp;
        __threadfence();
        int old = atomicAdd(&g_done, 1);
        s_last = (old == NBLK - 1) ? 1 : 0;
    }
    __syncthreads();

    if (s_last) {
        float F = 0.0f, D = 0.0f, A = 0.0f, C = 0.0f;
        #pragma unroll
        for (int k = 0; k < NBLK / NTHR; ++k) {
            float4 v = __ldcg(&g_part[tid + k * NTHR]);
            F += v.x; D += v.y; A += v.z; C += v.w;
        }
        #pragma unroll
        for (int o = 16; o > 0; o >>= 1) {
            F += __shfl_down_sync(0xffffffffu, F, o);
            D += __shfl_down_sync(0xffffffffu, D, o);
            A += __shfl_down_sync(0xffffffffu, A, o);
            C += __shfl_down_sync(0xffffffffu, C, o);
        }
        if (lane == 0) { s_w[warp][0] = F; s_w[warp][1] = D; s_w[warp][2] = A; s_w[warp][3] = C; }
        __syncthreads();
        if (tid == 0) {
            F = 0.0f; D = 0.0f; A = 0.0f; C = 0.0f;
            #pragma unroll
            for (int w = 0; w < 4; ++w) {
                F += s_w[w][0]; D += s_w[w][1];
                A += s_w[w][2]; C += s_w[w][3];
            }
            float flatness_loss  = -(F / (float)N_PTS);
            float alignment_loss = (C > 0.0f) ? (A / C) : 0.0f;
            float density_loss   = D / (float)N_PTS;
            out[0] = flatness_loss + 0.5f * alignment_loss + 0.2f * density_loss;
            g_done = 0;
        }
        // restore bucket counters for next graph replay
        #pragma unroll
        for (int k = 0; k < NCELLS / NTHR; ++k) g_cnt[tid + k * NTHR] = 0;
    }
}

// ---------------- launch ----------------
extern "C" void kernel_launch(void* const* d_in, const int* in_sizes, int n_in,
                              void* d_out, int out_size) {
    const float*  positions = (const float*)d_in[0];
    const float4* rotations = (const float4*)d_in[1];
    const float*  scales    = (const float*)d_in[2];
    const float*  opacity   = (const float*)d_in[3];
    float* out = (float*)d_out;

    scatter_k<<<N_PTS / 256, 256>>>(positions, rotations, scales);
    main_k<<<NBLK, NTHR>>>(positions, opacity, out);
}